// round 15
// baseline (speedup 1.0000x reference)
#include <cuda_runtime.h>
#include <cuda_fp16.h>
#include <math.h>
#include <stdint.h>

#define BATCH 4
#define CH    128
#define HH    128
#define WW    128
#define HWQ   16384
#define NHEAD 8
#define NPNT  8
#define NOFF  128
#define NATT  64
#define MAXRES 10.0f

// k_val/k_out strides
#define LDA136 136
#define LDB136 136
#define LDA133 133
// k1 strides
#define K1_LDA 132
#define K1_LDB 200

// ---- scratch ----
// d_val_h layout: (B, nh, HWQ, 16) fp16 — head-major so bilinear corner pairs
// (x, x+1) are 32B apart (same/adjacent 128B line) instead of 256B.
__device__ __half    d_val_h[(size_t)BATCH * NHEAD * HWQ * 16];
__device__ float     d_agg [(size_t)BATCH * HWQ * CH];
__device__ float2    d_loc [(size_t)BATCH * HWQ * NATT];
__device__ float     d_attn[(size_t)BATCH * HWQ * NATT];
__device__ uint32_t  d_PBH[64 * 192];   // pre-split B hi (bf16x2 per k-pair)
__device__ uint32_t  d_PBL[64 * 192];   // pre-split B lo

// ============================================================================
// helpers
// ============================================================================
__device__ __forceinline__ void mma_tf32(float* c, uint32_t a0, uint32_t a1,
                                         uint32_t a2, uint32_t a3,
                                         uint32_t b0, uint32_t b1) {
    asm volatile(
        "mma.sync.aligned.m16n8k8.row.col.f32.tf32.tf32.f32 "
        "{%0,%1,%2,%3},{%4,%5,%6,%7},{%8,%9},{%0,%1,%2,%3};"
        : "+f"(c[0]), "+f"(c[1]), "+f"(c[2]), "+f"(c[3])
        : "r"(a0), "r"(a1), "r"(a2), "r"(a3), "r"(b0), "r"(b1));
}
__device__ __forceinline__ void mma_bf16(float* c, const uint32_t* a,
                                         uint32_t b0, uint32_t b1) {
    asm volatile(
        "mma.sync.aligned.m16n8k16.row.col.f32.bf16.bf16.f32 "
        "{%0,%1,%2,%3},{%4,%5,%6,%7},{%8,%9},{%0,%1,%2,%3};"
        : "+f"(c[0]), "+f"(c[1]), "+f"(c[2]), "+f"(c[3])
        : "r"(a[0]), "r"(a[1]), "r"(a[2]), "r"(a[3]), "r"(b0), "r"(b1));
}
__device__ __forceinline__ uint32_t fbrna(float f) {
    uint32_t r;
    asm("cvt.rna.tf32.f32 %0, %1;" : "=r"(r) : "f"(f));
    return r;
}
__device__ __forceinline__ uint32_t bf16x2(float hi, float lo) {
    uint32_t r;
    asm("cvt.rn.bf16x2.f32 %0, %1, %2;" : "=r"(r) : "f"(hi), "f"(lo));
    return r;
}
__device__ __forceinline__ void cp16(uint32_t dst, const void* src) {
    asm volatile("cp.async.ca.shared.global [%0], [%1], 16;" :: "r"(dst), "l"(src));
}
__device__ __forceinline__ void cp4(uint32_t dst, const void* src) {
    asm volatile("cp.async.ca.shared.global [%0], [%1], 4;" :: "r"(dst), "l"(src));
}
#define CP_COMMIT() asm volatile("cp.async.commit_group;" ::: "memory")
#define CP_WAIT1()  asm volatile("cp.async.wait_group 1;" ::: "memory")
#define CP_WAIT0()  asm volatile("cp.async.wait_group 0;" ::: "memory")

// ============================================================================
// prep_B: split [W_off|W_attn] into packed bf16x2 hi/lo per k-pair.
// ============================================================================
__global__ void prep_B(const float* __restrict__ W_off,
                       const float* __restrict__ W_attn)
{
    int idx = blockIdx.x * 256 + threadIdx.x;   // < 12288
    int p = idx / 192, n = idx % 192;
    float v0, v1;
    if (n < NOFF) {
        v0 = W_off[(size_t)(2*p)   * NOFF + n];
        v1 = W_off[(size_t)(2*p+1) * NOFF + n];
    } else {
        v0 = W_attn[(size_t)(2*p)   * NATT + (n - NOFF)];
        v1 = W_attn[(size_t)(2*p+1) * NATT + (n - NOFF)];
    }
    uint32_t h = bf16x2(v1, v0);
    float h0 = __uint_as_float((h & 0xFFFFu) << 16);
    float h1 = __uint_as_float(h & 0xFFFF0000u);
    d_PBH[idx] = h;
    d_PBL[idx] = bf16x2(v1 - h1, v0 - h0);
}

// ============================================================================
// Kernel 1: ext @ [W_off|W_attn]  (M=128/block, N=192, K=128)
// bf16 m16n8k16 3-term (AhBh + AlBh + AhBl), B pre-split.
// ============================================================================
#define K1_ABUF (32*K1_LDA)              // 4224 u32 (raw fp32 A)
#define K1_BBUF (16*K1_LDB)              // 3200 u32 per array
#define K1_STG  (K1_ABUF + 2*K1_BBUF)    // 10624 u32 per buffer

__global__ __launch_bounds__(256, 2) void k1_offattn(
    const float* __restrict__ ext, const float* __restrict__ flow,
    const float* __restrict__ b_off, const float* __restrict__ b_attn)
{
    extern __shared__ float sm[];
    const int tid  = threadIdx.x;
    const int lane = tid & 31;
    const int warp = tid >> 5;
    const int mw   = warp & 3;
    const int nw   = warp >> 2;
    const int g    = lane >> 2;
    const int tq   = lane & 3;
    const int row0 = blockIdx.x * 128;
    const int b    = row0 / HWQ;
    const int q0   = row0 % HWQ;
    const uint32_t smb = (uint32_t)__cvta_generic_to_shared(sm);

    float acc[2][12][4];
#pragma unroll
    for (int t = 0; t < 2; ++t)
#pragma unroll
        for (int j = 0; j < 12; ++j)
#pragma unroll
            for (int v = 0; v < 4; ++v) acc[t][j][v] = 0.f;

    auto stage = [&](int kc, int buf) {
        uint32_t ab = smb + (uint32_t)(buf*K1_STG)*4u;
        const float* srcA = ext + ((size_t)b*CH + kc*32)*HWQ + q0;
#pragma unroll
        for (int it = 0; it < 4; ++it) {
            int e = tid + it*256;
            int k = e >> 5, c4 = e & 31;
            cp16(ab + (uint32_t)(k*K1_LDA + c4*4)*4u, srcA + (size_t)k*HWQ + c4*4);
        }
        uint32_t bb = smb + (uint32_t)(buf*K1_STG + K1_ABUF)*4u;
#pragma unroll
        for (int it = 0; it < 6; ++it) {
            int e = tid + it*256;              // < 1536
            int arr = (e >= 768);
            int e2 = e - arr*768;
            int r = e2 / 48, ch = e2 % 48;
            const uint32_t* src = (arr ? d_PBL : d_PBH) + (size_t)(kc*16 + r)*192 + ch*4;
            cp16(bb + (uint32_t)(arr*K1_BBUF + r*K1_LDB + ch*4)*4u, src);
        }
    };

    stage(0, 0); CP_COMMIT();
    for (int kc = 0; kc < 4; ++kc) {
        if (kc < 3) { stage(kc+1, (kc+1)&1); CP_COMMIT(); CP_WAIT1(); }
        else CP_WAIT0();
        __syncthreads();
        const float*    As  = sm + (kc&1)*K1_STG;
        const uint32_t* BHs = (const uint32_t*)(As + K1_ABUF);
        const uint32_t* BLs = BHs + K1_BBUF;

#pragma unroll
        for (int kh = 0; kh < 2; ++kh) {
            const int ka = kh*16 + 2*tq;
            const int lp = kh*8 + tq;
            uint32_t ah[2][4], al[2][4];
#pragma unroll
            for (int t = 0; t < 2; ++t) {
                int m = mw*32 + t*16 + g;
#pragma unroll
                for (int f = 0; f < 4; ++f) {
                    int kk = ka + (f >> 1)*8;
                    int mm = m + (f & 1)*8;
                    float v0 = As[kk*K1_LDA + mm];
                    float v1 = As[(kk+1)*K1_LDA + mm];
                    uint32_t u0 = __float_as_uint(v0), u1 = __float_as_uint(v1);
                    ah[t][f] = __byte_perm(u0, u1, 0x7632);
                    float h0 = __uint_as_float(u0 & 0xFFFF0000u);
                    float h1 = __uint_as_float(u1 & 0xFFFF0000u);
                    al[t][f] = bf16x2(v1 - h1, v0 - h0);
                }
            }
#pragma unroll
            for (int j = 0; j < 12; ++j) {
                int n = (j < 8) ? (nw*64 + j*8 + g)
                                : (NOFF + nw*32 + (j-8)*8 + g);
                uint32_t bh0 = BHs[lp*K1_LDB + n];
                uint32_t bh1 = BHs[(lp+4)*K1_LDB + n];
                uint32_t bl0 = BLs[lp*K1_LDB + n];
                uint32_t bl1 = BLs[(lp+4)*K1_LDB + n];
#pragma unroll
                for (int t = 0; t < 2; ++t) {
                    mma_bf16(acc[t][j], ah[t], bh0, bh1);
                    mma_bf16(acc[t][j], al[t], bh0, bh1);
                    mma_bf16(acc[t][j], ah[t], bl0, bl1);
                }
            }
        }
        if (kc < 3) __syncthreads();
    }

    // ---- epilogue ----
    int   qrow[4]; float fxv[4], fyv[4]; float wiv[4], hiv[4];
#pragma unroll
    for (int t = 0; t < 2; ++t)
#pragma unroll
        for (int rr = 0; rr < 2; ++rr) {
            int r  = mw*32 + t*16 + g + rr*8;
            int qq = q0 + r;
            int ri = t*2 + rr;
            qrow[ri] = qq;
            fxv[ri] = __ldg(&flow[(size_t)b*2*HWQ + qq]);
            fyv[ri] = __ldg(&flow[(size_t)b*2*HWQ + HWQ + qq]);
            wiv[ri] = (float)(qq & (WW-1));
            hiv[ri] = (float)((qq >> 7) & (HH-1));
        }

#pragma unroll
    for (int j = 0; j < 8; ++j) {
        int c = nw*64 + j*8 + 2*tq;
        int n = c >> 1;
        float b0v = __ldg(&b_off[c]), b1v = __ldg(&b_off[c+1]);
#pragma unroll
        for (int t = 0; t < 2; ++t)
#pragma unroll
            for (int rr = 0; rr < 2; ++rr) {
                int ri = t*2 + rr;
                float ox = MAXRES * tanhf(acc[t][j][rr*2]   + b0v);
                float oy = MAXRES * tanhf(acc[t][j][rr*2+1] + b1v);
                float lx = (wiv[ri] + 0.5f + fxv[ri] + ox) * (1.f/WW);
                float ly = (hiv[ri] + 0.5f + fyv[ri] + oy) * (1.f/HH);
                d_loc[((size_t)b*HWQ + qrow[ri])*NATT + n] = make_float2(lx, ly);
            }
    }
#pragma unroll
    for (int j = 8; j < 12; ++j) {
        int ca = nw*32 + (j-8)*8 + 2*tq;
        float ba0 = __ldg(&b_attn[ca]), ba1 = __ldg(&b_attn[ca+1]);
#pragma unroll
        for (int t = 0; t < 2; ++t)
#pragma unroll
            for (int rr = 0; rr < 2; ++rr) {
                float v0 = acc[t][j][rr*2]   + ba0;
                float v1 = acc[t][j][rr*2+1] + ba1;
                float mx = fmaxf(v0, v1);
                mx = fmaxf(mx, __shfl_xor_sync(0xffffffffu, mx, 1));
                mx = fmaxf(mx, __shfl_xor_sync(0xffffffffu, mx, 2));
                float e0 = __expf(v0 - mx), e1 = __expf(v1 - mx);
                float s = e0 + e1;
                s += __shfl_xor_sync(0xffffffffu, s, 1);
                s += __shfl_xor_sync(0xffffffffu, s, 2);
                float inv = 1.f / s;
                *(float2*)&d_attn[((size_t)b*HWQ + qrow[t*2+rr])*NATT + ca] =
                    make_float2(e0*inv, e1*inv);
            }
    }
}

// ============================================================================
// Kernel 2: val = nbr @ W_val + b_val  (N=128), single-pass tf32.
// fp16 output in HEAD-MAJOR layout (B, nh, HWQ, 16).
// ============================================================================
#define KV_ABUF (32*LDA136)
#define KV_BBUF (32*LDB136)
#define KV_STG  (KV_ABUF + KV_BBUF)

__global__ __launch_bounds__(256, 2) void k_val(
    const float* __restrict__ nbr,
    const float* __restrict__ W_val, const float* __restrict__ b_val)
{
    extern __shared__ float sm[];
    const int tid  = threadIdx.x;
    const int lane = tid & 31;
    const int warp = tid >> 5;
    const int mw   = warp & 3;
    const int nw   = warp >> 2;
    const int g    = lane >> 2;
    const int tq   = lane & 3;
    const int row0 = blockIdx.x * 128;
    const int b    = row0 / HWQ;
    const int q0   = row0 % HWQ;
    const uint32_t smb = (uint32_t)__cvta_generic_to_shared(sm);

    float acc[2][8][4];
#pragma unroll
    for (int t = 0; t < 2; ++t)
#pragma unroll
        for (int j = 0; j < 8; ++j)
#pragma unroll
            for (int v = 0; v < 4; ++v) acc[t][j][v] = 0.f;

    auto stage = [&](int kc, int buf) {
        uint32_t ab = smb + (uint32_t)(buf*KV_STG)*4u;
        const float* srcA = nbr + ((size_t)b*CH + kc*32)*HWQ + q0;
#pragma unroll
        for (int it = 0; it < 4; ++it) {
            int e = tid + it*256;
            int k = e >> 5, c4 = e & 31;
            cp16(ab + (uint32_t)(k*LDA136 + c4*4)*4u, srcA + (size_t)k*HWQ + c4*4);
        }
        uint32_t bb = smb + (uint32_t)(buf*KV_STG + KV_ABUF)*4u;
#pragma unroll
        for (int it = 0; it < 4; ++it) {
            int e = tid + it*256;
            int k = e >> 5, c4 = e & 31;
            cp16(bb + (uint32_t)(k*LDB136 + c4*4)*4u,
                 W_val + (size_t)(kc*32 + k)*CH + c4*4);
        }
    };

    stage(0, 0); CP_COMMIT();
    for (int kc = 0; kc < 4; ++kc) {
        if (kc < 3) { stage(kc+1, (kc+1)&1); CP_COMMIT(); CP_WAIT1(); }
        else CP_WAIT0();
        __syncthreads();
        const float* As = sm + (kc&1)*KV_STG;
        const float* Bs = As + KV_ABUF;

#pragma unroll
        for (int k8 = 0; k8 < 4; ++k8) {
            const int kr = k8*8 + tq;
            uint32_t av[2][4];
#pragma unroll
            for (int t = 0; t < 2; ++t) {
                int m = mw*32 + t*16 + g;
                av[t][0] = fbrna(As[kr*LDA136 + m]);
                av[t][1] = fbrna(As[kr*LDA136 + m + 8]);
                av[t][2] = fbrna(As[(kr+4)*LDA136 + m]);
                av[t][3] = fbrna(As[(kr+4)*LDA136 + m + 8]);
            }
#pragma unroll
            for (int j = 0; j < 8; ++j) {
                int n = nw*64 + j*8 + g;
                uint32_t b0 = fbrna(Bs[kr*LDB136 + n]);
                uint32_t b1 = fbrna(Bs[(kr+4)*LDB136 + n]);
#pragma unroll
                for (int t = 0; t < 2; ++t)
                    mma_tf32(acc[t][j], av[t][0],av[t][1],av[t][2],av[t][3], b0,b1);
            }
        }
        if (kc < 3) __syncthreads();
    }

    // epilogue: store to head-major (B, nh, HWQ, 16)
#pragma unroll
    for (int j = 0; j < 8; ++j) {
        int c  = nw*64 + j*8 + 2*tq;      // 0..127
        int h  = c >> 4;                   // head
        int ch = c & 15;                   // channel within head (even)
        float b0v = __ldg(&b_val[c]), b1v = __ldg(&b_val[c+1]);
        __half* dsth = d_val_h + ((size_t)(b*NHEAD + h) * HWQ) * 16 + ch;
#pragma unroll
        for (int t = 0; t < 2; ++t)
#pragma unroll
            for (int rr = 0; rr < 2; ++rr) {
                int q = q0 + mw*32 + t*16 + g + rr*8;
                __half2 hv = __floats2half2_rn(acc[t][j][rr*2] + b0v,
                                               acc[t][j][rr*2+1] + b1v);
                *(__half2*)(dsth + (size_t)q*16) = hv;
            }
    }
}

// ============================================================================
// Kernel 3: bilinear gather from head-major fp16 values.
// 256 threads = 16 q x (8 heads x 2 channel-halves). Corner x-pairs are
// 32B apart -> ~2.5 lines per (q,h,p) instead of 4.
// ============================================================================
__device__ __forceinline__ void gacc(float w, const __half* p, float* acc) {
    uint4 gg = __ldg((const uint4*)p);
    float2 f;
    f = __half22float2(*(__half2*)&gg.x); acc[0]=fmaf(w,f.x,acc[0]); acc[1]=fmaf(w,f.y,acc[1]);
    f = __half22float2(*(((__half2*)&gg.x)+1)); acc[2]=fmaf(w,f.x,acc[2]); acc[3]=fmaf(w,f.y,acc[3]);
    f = __half22float2(*(__half2*)&gg.z); acc[4]=fmaf(w,f.x,acc[4]); acc[5]=fmaf(w,f.y,acc[5]);
    f = __half22float2(*(((__half2*)&gg.z)+1)); acc[6]=fmaf(w,f.x,acc[6]); acc[7]=fmaf(w,f.y,acc[7]);
}

__global__ __launch_bounds__(256) void k_gather()
{
    __shared__ float2 loc_s[16][NATT];
    __shared__ float  attn_s[16][NATT];
    const int tx = threadIdx.x;
    const size_t base = (size_t)blockIdx.x * 16;

    for (int i = tx; i < 1024; i += 256) {
        int tq = i >> 6, n = i & 63;
        loc_s[tq][n]  = d_loc [(base + tq)*NATT + n];
        attn_s[tq][n] = d_attn[(base + tq)*NATT + n];
    }
    __syncthreads();

    const int tq = tx >> 4;                 // q within block
    const int s  = tx & 15;                 // h*2 + channel-half
    const int h  = s >> 1;
    const int cc = s & 1;
    const size_t row = base + tq;
    const int b  = (int)(row >> 14);
    const __half* vb = d_val_h + ((size_t)(b*NHEAD + h) * HWQ) * 16 + cc*8;

    float acc[8];
#pragma unroll
    for (int i = 0; i < 8; ++i) acc[i] = 0.f;

#pragma unroll
    for (int p = 0; p < NPNT; ++p) {
        int n = h*NPNT + p;
        float2 l = loc_s[tq][n];
        float  a = attn_s[tq][n];
        float x = l.x * (float)WW - 0.5f;
        float y = l.y * (float)HH - 0.5f;
        float x0f = floorf(x), y0f = floorf(y);
        float wx = x - x0f,    wy = y - y0f;
        int x0 = (int)x0f, y0 = (int)y0f;
        int x1 = x0 + 1,   y1 = y0 + 1;
        bool xv0 = (x0 >= 0) & (x0 < WW);
        bool xv1 = (x1 >= 0) & (x1 < WW);
        bool yv0 = (y0 >= 0) & (y0 < HH);
        bool yv1 = (y1 >= 0) & (y1 < HH);
        float w00 = (1.f-wx)*(1.f-wy) * a;
        float w10 = wx*(1.f-wy) * a;
        float w01 = (1.f-wx)*wy * a;
        float w11 = wx*wy * a;
        if (xv0 & yv0) gacc(w00, vb + (size_t)(y0*WW + x0)*16, acc);
        if (xv1 & yv0) gacc(w10, vb + (size_t)(y0*WW + x1)*16, acc);
        if (xv0 & yv1) gacc(w01, vb + (size_t)(y1*WW + x0)*16, acc);
        if (xv1 & yv1) gacc(w11, vb + (size_t)(y1*WW + x1)*16, acc);
    }
    // d_agg stays (B, Q, 128): channels s*8 .. s*8+8
    float* dst = d_agg + row*CH + s*8;
    *(float4*)dst     = make_float4(acc[0], acc[1], acc[2], acc[3]);
    *(float4*)(dst+4) = make_float4(acc[4], acc[5], acc[6], acc[7]);
}

// ============================================================================
// Kernel 4: out = agg @ W_out + b_out (N=128), single-pass tf32,
// transposed store.
// ============================================================================
#define KO_ABUF (32*LDA133)
#define KO_BBUF (32*LDB136)
#define KO_STG  (KO_ABUF + KO_BBUF)

__global__ __launch_bounds__(256, 2) void k_out(
    const float* __restrict__ W_out, const float* __restrict__ b_out,
    float* __restrict__ out)
{
    extern __shared__ float sm[];
    const int tid  = threadIdx.x;
    const int lane = tid & 31;
    const int warp = tid >> 5;
    const int mw   = warp & 3;
    const int nw   = warp >> 2;
    const int g    = lane >> 2;
    const int tq   = lane & 3;
    const int row0 = blockIdx.x * 128;
    const int b    = row0 / HWQ;
    const int q0   = row0 % HWQ;
    const uint32_t smb = (uint32_t)__cvta_generic_to_shared(sm);

    float acc[2][8][4];
#pragma unroll
    for (int t = 0; t < 2; ++t)
#pragma unroll
        for (int j = 0; j < 8; ++j)
#pragma unroll
            for (int v = 0; v < 4; ++v) acc[t][j][v] = 0.f;

    auto stage = [&](int kc, int buf) {
        uint32_t ab = smb + (uint32_t)(buf*KO_STG)*4u;
        const float* srcA = d_agg + (size_t)row0*CH + kc*32;
#pragma unroll
        for (int it = 0; it < 16; ++it) {
            int e = tid + it*256;
            int m = e >> 5, k = e & 31;
            cp4(ab + (uint32_t)(k*LDA133 + m)*4u, srcA + (size_t)m*CH + k);
        }
        uint32_t bb = smb + (uint32_t)(buf*KO_STG + KO_ABUF)*4u;
#pragma unroll
        for (int it = 0; it < 4; ++it) {
            int e = tid + it*256;
            int k = e >> 5, c4 = e & 31;
            cp16(bb + (uint32_t)(k*LDB136 + c4*4)*4u,
                 W_out + (size_t)(kc*32 + k)*CH + c4*4);
        }
    };

    stage(0, 0); CP_COMMIT();
    for (int kc = 0; kc < 4; ++kc) {
        if (kc < 3) { stage(kc+1, (kc+1)&1); CP_COMMIT(); CP_WAIT1(); }
        else CP_WAIT0();
        __syncthreads();
        const float* As = sm + (kc&1)*KO_STG;
        const float* Bs = As + KO_ABUF;

#pragma unroll
        for (int k8 = 0; k8 < 4; ++k8) {
            const int kr = k8*8 + tq;
            uint32_t av[2][4];
#pragma unroll
            for (int t = 0; t < 2; ++t) {
                int m = mw*32 + t*16 + g;
                av[t][0] = fbrna(As[kr*LDA133 + m]);
                av[t][1] = fbrna(As[kr*LDA133 + m + 8]);
                av[t][2] = fbrna(As[(kr+4)*LDA133 + m]);
                av[t][3] = fbrna(As[(kr+4)*LDA133 + m + 8]);
            }
#pragma unroll
            for (int j = 0; j < 8; ++j) {
                int n = nw*64 + j*8 + g;
                uint32_t b0 = fbrna(Bs[kr*LDB136 + n]);
                uint32_t b1 = fbrna(Bs[(kr+4)*LDB136 + n]);
#pragma unroll
                for (int t = 0; t < 2; ++t)
                    mma_tf32(acc[t][j], av[t][0],av[t][1],av[t][2],av[t][3], b0,b1);
            }
        }
        __syncthreads();
    }

    float* buf = sm;                       // reuse; 128*129 floats
#pragma unroll
    for (int j = 0; j < 8; ++j) {
        int c = nw*64 + j*8 + 2*tq;
        float b0v = __ldg(&b_out[c]), b1v = __ldg(&b_out[c+1]);
#pragma unroll
        for (int t = 0; t < 2; ++t)
#pragma unroll
            for (int rr = 0; rr < 2; ++rr) {
                int m = mw*32 + t*16 + g + rr*8;
                buf[m*129 + c]     = acc[t][j][rr*2]   + b0v;
                buf[m*129 + c + 1] = acc[t][j][rr*2+1] + b1v;
            }
    }
    __syncthreads();
    for (int idx = tid; idx < 128*128; idx += 256) {
        int m = idx & 127, n = idx >> 7;
        out[(size_t)b*CH*HWQ + (size_t)n*HWQ + q0 + m] = buf[m*129 + n];
    }
}

// ============================================================================
extern "C" void kernel_launch(void* const* d_in, const int* in_sizes, int n_in,
                              void* d_out, int out_size)
{
    const float* nbr    = (const float*)d_in[0];
    const float* ext    = (const float*)d_in[1];
    const float* flow   = (const float*)d_in[2];
    const float* W_off  = (const float*)d_in[3];
    const float* b_off  = (const float*)d_in[4];
    const float* W_attn = (const float*)d_in[5];
    const float* b_attn = (const float*)d_in[6];
    const float* W_val  = (const float*)d_in[7];
    const float* b_val  = (const float*)d_in[8];
    const float* W_out  = (const float*)d_in[9];
    const float* b_out  = (const float*)d_in[10];
    float* out = (float*)d_out;

    const int SM_K1 = 2*K1_STG*4;
    const int SM_KV = 2*KV_STG*4;
    const int SM_KO = 2*KO_STG*4;

    cudaFuncSetAttribute(k1_offattn, cudaFuncAttributeMaxDynamicSharedMemorySize, SM_K1);
    cudaFuncSetAttribute(k_val,      cudaFuncAttributeMaxDynamicSharedMemorySize, SM_KV);
    cudaFuncSetAttribute(k_out,      cudaFuncAttributeMaxDynamicSharedMemorySize, SM_KO);

    const int nblk = BATCH * HWQ / 128;   // 512

    prep_B    <<<48, 256>>>(W_off, W_attn);
    k1_offattn<<<nblk, 256, SM_K1>>>(ext, flow, b_off, b_attn);
    k_val     <<<nblk, 256, SM_KV>>>(nbr, W_val, b_val);
    k_gather  <<<BATCH * HWQ / 16, 256>>>();
    k_out     <<<nblk, 256, SM_KO>>>(W_out, b_out, out);
}

// round 16
// speedup vs baseline: 1.1156x; 1.1156x over previous
#include <cuda_runtime.h>
#include <cuda_fp16.h>
#include <math.h>
#include <stdint.h>

#define BATCH 4
#define CH    128
#define HH    128
#define WW    128
#define HWQ   16384
#define NHEAD 8
#define NPNT  8
#define NOFF  128
#define NATT  64
#define MAXRES 10.0f

// k_val/k_out strides
#define LDA136 136
#define LDB136 136
#define LDA133 133
// k1 strides
#define K1_LDA 132
#define K1_LDB 200

// ---- scratch ----
// d_val_h layout: (B, nh, HWQ, 16) fp16 — head-major so the (x0,x1) corner
// pair of a bilinear sample is one contiguous 64B span.
__device__ __half    d_val_h[(size_t)BATCH * NHEAD * HWQ * 16];
__device__ float     d_agg [(size_t)BATCH * HWQ * CH];
__device__ float2    d_loc [(size_t)BATCH * HWQ * NATT];
__device__ float     d_attn[(size_t)BATCH * HWQ * NATT];
__device__ uint32_t  d_PBH[64 * 192];   // pre-split B hi (bf16x2 per k-pair)
__device__ uint32_t  d_PBL[64 * 192];   // pre-split B lo

// ============================================================================
// helpers
// ============================================================================
__device__ __forceinline__ void mma_tf32(float* c, uint32_t a0, uint32_t a1,
                                         uint32_t a2, uint32_t a3,
                                         uint32_t b0, uint32_t b1) {
    asm volatile(
        "mma.sync.aligned.m16n8k8.row.col.f32.tf32.tf32.f32 "
        "{%0,%1,%2,%3},{%4,%5,%6,%7},{%8,%9},{%0,%1,%2,%3};"
        : "+f"(c[0]), "+f"(c[1]), "+f"(c[2]), "+f"(c[3])
        : "r"(a0), "r"(a1), "r"(a2), "r"(a3), "r"(b0), "r"(b1));
}
__device__ __forceinline__ void mma_bf16(float* c, const uint32_t* a,
                                         uint32_t b0, uint32_t b1) {
    asm volatile(
        "mma.sync.aligned.m16n8k16.row.col.f32.bf16.bf16.f32 "
        "{%0,%1,%2,%3},{%4,%5,%6,%7},{%8,%9},{%0,%1,%2,%3};"
        : "+f"(c[0]), "+f"(c[1]), "+f"(c[2]), "+f"(c[3])
        : "r"(a[0]), "r"(a[1]), "r"(a[2]), "r"(a[3]), "r"(b0), "r"(b1));
}
__device__ __forceinline__ uint32_t fbrna(float f) {
    uint32_t r;
    asm("cvt.rna.tf32.f32 %0, %1;" : "=r"(r) : "f"(f));
    return r;
}
__device__ __forceinline__ uint32_t bf16x2(float hi, float lo) {
    uint32_t r;
    asm("cvt.rn.bf16x2.f32 %0, %1, %2;" : "=r"(r) : "f"(hi), "f"(lo));
    return r;
}
__device__ __forceinline__ void cp16(uint32_t dst, const void* src) {
    asm volatile("cp.async.ca.shared.global [%0], [%1], 16;" :: "r"(dst), "l"(src));
}
__device__ __forceinline__ void cp4(uint32_t dst, const void* src) {
    asm volatile("cp.async.ca.shared.global [%0], [%1], 4;" :: "r"(dst), "l"(src));
}
#define CP_COMMIT() asm volatile("cp.async.commit_group;" ::: "memory")
#define CP_WAIT1()  asm volatile("cp.async.wait_group 1;" ::: "memory")
#define CP_WAIT0()  asm volatile("cp.async.wait_group 0;" ::: "memory")

// ============================================================================
// prep_B: split [W_off|W_attn] into packed bf16x2 hi/lo per k-pair.
// ============================================================================
__global__ void prep_B(const float* __restrict__ W_off,
                       const float* __restrict__ W_attn)
{
    int idx = blockIdx.x * 256 + threadIdx.x;   // < 12288
    int p = idx / 192, n = idx % 192;
    float v0, v1;
    if (n < NOFF) {
        v0 = W_off[(size_t)(2*p)   * NOFF + n];
        v1 = W_off[(size_t)(2*p+1) * NOFF + n];
    } else {
        v0 = W_attn[(size_t)(2*p)   * NATT + (n - NOFF)];
        v1 = W_attn[(size_t)(2*p+1) * NATT + (n - NOFF)];
    }
    uint32_t h = bf16x2(v1, v0);
    float h0 = __uint_as_float((h & 0xFFFFu) << 16);
    float h1 = __uint_as_float(h & 0xFFFF0000u);
    d_PBH[idx] = h;
    d_PBL[idx] = bf16x2(v1 - h1, v0 - h0);
}

// ============================================================================
// Kernel 1: ext @ [W_off|W_attn]  (M=128/block, N=192, K=128)
// bf16 m16n8k16 3-term (AhBh + AlBh + AhBl), B pre-split.
// ============================================================================
#define K1_ABUF (32*K1_LDA)
#define K1_BBUF (16*K1_LDB)
#define K1_STG  (K1_ABUF + 2*K1_BBUF)

__global__ __launch_bounds__(256, 2) void k1_offattn(
    const float* __restrict__ ext, const float* __restrict__ flow,
    const float* __restrict__ b_off, const float* __restrict__ b_attn)
{
    extern __shared__ float sm[];
    const int tid  = threadIdx.x;
    const int lane = tid & 31;
    const int warp = tid >> 5;
    const int mw   = warp & 3;
    const int nw   = warp >> 2;
    const int g    = lane >> 2;
    const int tq   = lane & 3;
    const int row0 = blockIdx.x * 128;
    const int b    = row0 / HWQ;
    const int q0   = row0 % HWQ;
    const uint32_t smb = (uint32_t)__cvta_generic_to_shared(sm);

    float acc[2][12][4];
#pragma unroll
    for (int t = 0; t < 2; ++t)
#pragma unroll
        for (int j = 0; j < 12; ++j)
#pragma unroll
            for (int v = 0; v < 4; ++v) acc[t][j][v] = 0.f;

    auto stage = [&](int kc, int buf) {
        uint32_t ab = smb + (uint32_t)(buf*K1_STG)*4u;
        const float* srcA = ext + ((size_t)b*CH + kc*32)*HWQ + q0;
#pragma unroll
        for (int it = 0; it < 4; ++it) {
            int e = tid + it*256;
            int k = e >> 5, c4 = e & 31;
            cp16(ab + (uint32_t)(k*K1_LDA + c4*4)*4u, srcA + (size_t)k*HWQ + c4*4);
        }
        uint32_t bb = smb + (uint32_t)(buf*K1_STG + K1_ABUF)*4u;
#pragma unroll
        for (int it = 0; it < 6; ++it) {
            int e = tid + it*256;
            int arr = (e >= 768);
            int e2 = e - arr*768;
            int r = e2 / 48, ch = e2 % 48;
            const uint32_t* src = (arr ? d_PBL : d_PBH) + (size_t)(kc*16 + r)*192 + ch*4;
            cp16(bb + (uint32_t)(arr*K1_BBUF + r*K1_LDB + ch*4)*4u, src);
        }
    };

    stage(0, 0); CP_COMMIT();
    for (int kc = 0; kc < 4; ++kc) {
        if (kc < 3) { stage(kc+1, (kc+1)&1); CP_COMMIT(); CP_WAIT1(); }
        else CP_WAIT0();
        __syncthreads();
        const float*    As  = sm + (kc&1)*K1_STG;
        const uint32_t* BHs = (const uint32_t*)(As + K1_ABUF);
        const uint32_t* BLs = BHs + K1_BBUF;

#pragma unroll
        for (int kh = 0; kh < 2; ++kh) {
            const int ka = kh*16 + 2*tq;
            const int lp = kh*8 + tq;
            uint32_t ah[2][4], al[2][4];
#pragma unroll
            for (int t = 0; t < 2; ++t) {
                int m = mw*32 + t*16 + g;
#pragma unroll
                for (int f = 0; f < 4; ++f) {
                    int kk = ka + (f >> 1)*8;
                    int mm = m + (f & 1)*8;
                    float v0 = As[kk*K1_LDA + mm];
                    float v1 = As[(kk+1)*K1_LDA + mm];
                    uint32_t u0 = __float_as_uint(v0), u1 = __float_as_uint(v1);
                    ah[t][f] = __byte_perm(u0, u1, 0x7632);
                    float h0 = __uint_as_float(u0 & 0xFFFF0000u);
                    float h1 = __uint_as_float(u1 & 0xFFFF0000u);
                    al[t][f] = bf16x2(v1 - h1, v0 - h0);
                }
            }
#pragma unroll
            for (int j = 0; j < 12; ++j) {
                int n = (j < 8) ? (nw*64 + j*8 + g)
                                : (NOFF + nw*32 + (j-8)*8 + g);
                uint32_t bh0 = BHs[lp*K1_LDB + n];
                uint32_t bh1 = BHs[(lp+4)*K1_LDB + n];
                uint32_t bl0 = BLs[lp*K1_LDB + n];
                uint32_t bl1 = BLs[(lp+4)*K1_LDB + n];
#pragma unroll
                for (int t = 0; t < 2; ++t) {
                    mma_bf16(acc[t][j], ah[t], bh0, bh1);
                    mma_bf16(acc[t][j], al[t], bh0, bh1);
                    mma_bf16(acc[t][j], ah[t], bl0, bl1);
                }
            }
        }
        if (kc < 3) __syncthreads();
    }

    // ---- epilogue ----
    int   qrow[4]; float fxv[4], fyv[4]; float wiv[4], hiv[4];
#pragma unroll
    for (int t = 0; t < 2; ++t)
#pragma unroll
        for (int rr = 0; rr < 2; ++rr) {
            int r  = mw*32 + t*16 + g + rr*8;
            int qq = q0 + r;
            int ri = t*2 + rr;
            qrow[ri] = qq;
            fxv[ri] = __ldg(&flow[(size_t)b*2*HWQ + qq]);
            fyv[ri] = __ldg(&flow[(size_t)b*2*HWQ + HWQ + qq]);
            wiv[ri] = (float)(qq & (WW-1));
            hiv[ri] = (float)((qq >> 7) & (HH-1));
        }

#pragma unroll
    for (int j = 0; j < 8; ++j) {
        int c = nw*64 + j*8 + 2*tq;
        int n = c >> 1;
        float b0v = __ldg(&b_off[c]), b1v = __ldg(&b_off[c+1]);
#pragma unroll
        for (int t = 0; t < 2; ++t)
#pragma unroll
            for (int rr = 0; rr < 2; ++rr) {
                int ri = t*2 + rr;
                float ox = MAXRES * tanhf(acc[t][j][rr*2]   + b0v);
                float oy = MAXRES * tanhf(acc[t][j][rr*2+1] + b1v);
                float lx = (wiv[ri] + 0.5f + fxv[ri] + ox) * (1.f/WW);
                float ly = (hiv[ri] + 0.5f + fyv[ri] + oy) * (1.f/HH);
                d_loc[((size_t)b*HWQ + qrow[ri])*NATT + n] = make_float2(lx, ly);
            }
    }
#pragma unroll
    for (int j = 8; j < 12; ++j) {
        int ca = nw*32 + (j-8)*8 + 2*tq;
        float ba0 = __ldg(&b_attn[ca]), ba1 = __ldg(&b_attn[ca+1]);
#pragma unroll
        for (int t = 0; t < 2; ++t)
#pragma unroll
            for (int rr = 0; rr < 2; ++rr) {
                float v0 = acc[t][j][rr*2]   + ba0;
                float v1 = acc[t][j][rr*2+1] + ba1;
                float mx = fmaxf(v0, v1);
                mx = fmaxf(mx, __shfl_xor_sync(0xffffffffu, mx, 1));
                mx = fmaxf(mx, __shfl_xor_sync(0xffffffffu, mx, 2));
                float e0 = __expf(v0 - mx), e1 = __expf(v1 - mx);
                float s = e0 + e1;
                s += __shfl_xor_sync(0xffffffffu, s, 1);
                s += __shfl_xor_sync(0xffffffffu, s, 2);
                float inv = 1.f / s;
                *(float2*)&d_attn[((size_t)b*HWQ + qrow[t*2+rr])*NATT + ca] =
                    make_float2(e0*inv, e1*inv);
            }
    }
}

// ============================================================================
// Kernel 2: val = nbr @ W_val + b_val  (N=128), single-pass tf32.
// fp16 output in HEAD-MAJOR layout (B, nh, HWQ, 16).
// ============================================================================
#define KV_ABUF (32*LDA136)
#define KV_BBUF (32*LDB136)
#define KV_STG  (KV_ABUF + KV_BBUF)

__global__ __launch_bounds__(256, 2) void k_val(
    const float* __restrict__ nbr,
    const float* __restrict__ W_val, const float* __restrict__ b_val)
{
    extern __shared__ float sm[];
    const int tid  = threadIdx.x;
    const int lane = tid & 31;
    const int warp = tid >> 5;
    const int mw   = warp & 3;
    const int nw   = warp >> 2;
    const int g    = lane >> 2;
    const int tq   = lane & 3;
    const int row0 = blockIdx.x * 128;
    const int b    = row0 / HWQ;
    const int q0   = row0 % HWQ;
    const uint32_t smb = (uint32_t)__cvta_generic_to_shared(sm);

    float acc[2][8][4];
#pragma unroll
    for (int t = 0; t < 2; ++t)
#pragma unroll
        for (int j = 0; j < 8; ++j)
#pragma unroll
            for (int v = 0; v < 4; ++v) acc[t][j][v] = 0.f;

    auto stage = [&](int kc, int buf) {
        uint32_t ab = smb + (uint32_t)(buf*KV_STG)*4u;
        const float* srcA = nbr + ((size_t)b*CH + kc*32)*HWQ + q0;
#pragma unroll
        for (int it = 0; it < 4; ++it) {
            int e = tid + it*256;
            int k = e >> 5, c4 = e & 31;
            cp16(ab + (uint32_t)(k*LDA136 + c4*4)*4u, srcA + (size_t)k*HWQ + c4*4);
        }
        uint32_t bb = smb + (uint32_t)(buf*KV_STG + KV_ABUF)*4u;
#pragma unroll
        for (int it = 0; it < 4; ++it) {
            int e = tid + it*256;
            int k = e >> 5, c4 = e & 31;
            cp16(bb + (uint32_t)(k*LDB136 + c4*4)*4u,
                 W_val + (size_t)(kc*32 + k)*CH + c4*4);
        }
    };

    stage(0, 0); CP_COMMIT();
    for (int kc = 0; kc < 4; ++kc) {
        if (kc < 3) { stage(kc+1, (kc+1)&1); CP_COMMIT(); CP_WAIT1(); }
        else CP_WAIT0();
        __syncthreads();
        const float* As = sm + (kc&1)*KV_STG;
        const float* Bs = As + KV_ABUF;

#pragma unroll
        for (int k8 = 0; k8 < 4; ++k8) {
            const int kr = k8*8 + tq;
            uint32_t av[2][4];
#pragma unroll
            for (int t = 0; t < 2; ++t) {
                int m = mw*32 + t*16 + g;
                av[t][0] = fbrna(As[kr*LDA136 + m]);
                av[t][1] = fbrna(As[kr*LDA136 + m + 8]);
                av[t][2] = fbrna(As[(kr+4)*LDA136 + m]);
                av[t][3] = fbrna(As[(kr+4)*LDA136 + m + 8]);
            }
#pragma unroll
            for (int j = 0; j < 8; ++j) {
                int n = nw*64 + j*8 + g;
                uint32_t b0 = fbrna(Bs[kr*LDB136 + n]);
                uint32_t b1 = fbrna(Bs[(kr+4)*LDB136 + n]);
#pragma unroll
                for (int t = 0; t < 2; ++t)
                    mma_tf32(acc[t][j], av[t][0],av[t][1],av[t][2],av[t][3], b0,b1);
            }
        }
        if (kc < 3) __syncthreads();
    }

    // epilogue: store to head-major (B, nh, HWQ, 16)
#pragma unroll
    for (int j = 0; j < 8; ++j) {
        int c  = nw*64 + j*8 + 2*tq;
        int h  = c >> 4;
        int ch = c & 15;
        float b0v = __ldg(&b_val[c]), b1v = __ldg(&b_val[c+1]);
        __half* dsth = d_val_h + ((size_t)(b*NHEAD + h) * HWQ) * 16 + ch;
#pragma unroll
        for (int t = 0; t < 2; ++t)
#pragma unroll
            for (int rr = 0; rr < 2; ++rr) {
                int q = q0 + mw*32 + t*16 + g + rr*8;
                __half2 hv = __floats2half2_rn(acc[t][j][rr*2] + b0v,
                                               acc[t][j][rr*2+1] + b1v);
                *(__half2*)(dsth + (size_t)q*16) = hv;
            }
    }
}

// ============================================================================
// Kernel 3: bilinear gather — x-corner-fused loads.
// Warp = 1 q; 4 lanes per head = (x-corner, channel-half). Each lane issues
// ONE 16B load per y-row covering its quarter of the contiguous 64B
// (x0,x1) span -> 2 load instructions per (q,h,p) instead of 4, and warp
// lanes of one head share lines within the instruction. Final shfl_xor(2)
// combines the two x-corner partial sums.
// ============================================================================
__global__ __launch_bounds__(256) void k_gather()
{
    __shared__ float2 loc_s[8][NATT];
    __shared__ float  attn_s[8][NATT];
    const int tx = threadIdx.x;
    const size_t base = (size_t)blockIdx.x * 8;

    for (int i = tx; i < 512; i += 256) {
        int tq = i >> 6, n = i & 63;
        loc_s[tq][n]  = d_loc [(base + tq)*NATT + n];
        attn_s[tq][n] = d_attn[(base + tq)*NATT + n];
    }
    __syncthreads();

    const int tq  = tx >> 5;                // q within block (one warp per q)
    const int lane = tx & 31;
    const int h   = lane >> 2;
    const int cc  = lane & 3;
    const int xc  = cc >> 1;                // x-corner this lane handles
    const int chh = cc & 1;                 // channel half (8 ch)
    const size_t row = base + tq;
    const int b  = (int)(row >> 14);
    const __half* vb = d_val_h + ((size_t)(b*NHEAD + h) * HWQ) * 16 + chh*8;

    float acc[8];
#pragma unroll
    for (int i = 0; i < 8; ++i) acc[i] = 0.f;

#pragma unroll
    for (int p = 0; p < NPNT; ++p) {
        int n = h*NPNT + p;
        float2 l = loc_s[tq][n];
        float  a = attn_s[tq][n];
        float x = l.x * (float)WW - 0.5f;
        float y = l.y * (float)HH - 0.5f;
        float x0f = floorf(x), y0f = floorf(y);
        float wx = x - x0f,    wy = y - y0f;
        int xi = (int)x0f + xc;
        int y0 = (int)y0f;
        bool xv = (xi >= 0) & (xi < WW);
        float wxc = xc ? wx : (1.f - wx);
#pragma unroll
        for (int yr = 0; yr < 2; ++yr) {
            int yi = y0 + yr;
            float w = wxc * (yr ? wy : (1.f - wy)) * a;
            if (xv & (yi >= 0) & (yi < HH)) {
                uint4 gg = __ldg((const uint4*)(vb + (size_t)(yi*WW + xi)*16));
                float2 f;
                f = __half22float2(*(__half2*)&gg.x);
                acc[0]=fmaf(w,f.x,acc[0]); acc[1]=fmaf(w,f.y,acc[1]);
                f = __half22float2(*(((__half2*)&gg.x)+1));
                acc[2]=fmaf(w,f.x,acc[2]); acc[3]=fmaf(w,f.y,acc[3]);
                f = __half22float2(*(__half2*)&gg.z);
                acc[4]=fmaf(w,f.x,acc[4]); acc[5]=fmaf(w,f.y,acc[5]);
                f = __half22float2(*(((__half2*)&gg.z)+1));
                acc[6]=fmaf(w,f.x,acc[6]); acc[7]=fmaf(w,f.y,acc[7]);
            }
        }
    }
    // combine x0 + x1 partial sums (lanes differ in bit 1)
#pragma unroll
    for (int i = 0; i < 8; ++i)
        acc[i] += __shfl_xor_sync(0xffffffffu, acc[i], 2);

    if (xc == 0) {
        float* dst = d_agg + row*CH + h*16 + chh*8;
        *(float4*)dst     = make_float4(acc[0], acc[1], acc[2], acc[3]);
        *(float4*)(dst+4) = make_float4(acc[4], acc[5], acc[6], acc[7]);
    }
}

// ============================================================================
// Kernel 4: out = agg @ W_out + b_out (N=128), single-pass tf32,
// transposed store.
// ============================================================================
#define KO_ABUF (32*LDA133)
#define KO_BBUF (32*LDB136)
#define KO_STG  (KO_ABUF + KO_BBUF)

__global__ __launch_bounds__(256, 2) void k_out(
    const float* __restrict__ W_out, const float* __restrict__ b_out,
    float* __restrict__ out)
{
    extern __shared__ float sm[];
    const int tid  = threadIdx.x;
    const int lane = tid & 31;
    const int warp = tid >> 5;
    const int mw   = warp & 3;
    const int nw   = warp >> 2;
    const int g    = lane >> 2;
    const int tq   = lane & 3;
    const int row0 = blockIdx.x * 128;
    const int b    = row0 / HWQ;
    const int q0   = row0 % HWQ;
    const uint32_t smb = (uint32_t)__cvta_generic_to_shared(sm);

    float acc[2][8][4];
#pragma unroll
    for (int t = 0; t < 2; ++t)
#pragma unroll
        for (int j = 0; j < 8; ++j)
#pragma unroll
            for (int v = 0; v < 4; ++v) acc[t][j][v] = 0.f;

    auto stage = [&](int kc, int buf) {
        uint32_t ab = smb + (uint32_t)(buf*KO_STG)*4u;
        const float* srcA = d_agg + (size_t)row0*CH + kc*32;
#pragma unroll
        for (int it = 0; it < 16; ++it) {
            int e = tid + it*256;
            int m = e >> 5, k = e & 31;
            cp4(ab + (uint32_t)(k*LDA133 + m)*4u, srcA + (size_t)m*CH + k);
        }
        uint32_t bb = smb + (uint32_t)(buf*KO_STG + KO_ABUF)*4u;
#pragma unroll
        for (int it = 0; it < 4; ++it) {
            int e = tid + it*256;
            int k = e >> 5, c4 = e & 31;
            cp16(bb + (uint32_t)(k*LDB136 + c4*4)*4u,
                 W_out + (size_t)(kc*32 + k)*CH + c4*4);
        }
    };

    stage(0, 0); CP_COMMIT();
    for (int kc = 0; kc < 4; ++kc) {
        if (kc < 3) { stage(kc+1, (kc+1)&1); CP_COMMIT(); CP_WAIT1(); }
        else CP_WAIT0();
        __syncthreads();
        const float* As = sm + (kc&1)*KO_STG;
        const float* Bs = As + KO_ABUF;

#pragma unroll
        for (int k8 = 0; k8 < 4; ++k8) {
            const int kr = k8*8 + tq;
            uint32_t av[2][4];
#pragma unroll
            for (int t = 0; t < 2; ++t) {
                int m = mw*32 + t*16 + g;
                av[t][0] = fbrna(As[kr*LDA133 + m]);
                av[t][1] = fbrna(As[kr*LDA133 + m + 8]);
                av[t][2] = fbrna(As[(kr+4)*LDA133 + m]);
                av[t][3] = fbrna(As[(kr+4)*LDA133 + m + 8]);
            }
#pragma unroll
            for (int j = 0; j < 8; ++j) {
                int n = nw*64 + j*8 + g;
                uint32_t b0 = fbrna(Bs[kr*LDB136 + n]);
                uint32_t b1 = fbrna(Bs[(kr+4)*LDB136 + n]);
#pragma unroll
                for (int t = 0; t < 2; ++t)
                    mma_tf32(acc[t][j], av[t][0],av[t][1],av[t][2],av[t][3], b0,b1);
            }
        }
        __syncthreads();
    }

    float* buf = sm;                       // reuse; 128*129 floats
#pragma unroll
    for (int j = 0; j < 8; ++j) {
        int c = nw*64 + j*8 + 2*tq;
        float b0v = __ldg(&b_out[c]), b1v = __ldg(&b_out[c+1]);
#pragma unroll
        for (int t = 0; t < 2; ++t)
#pragma unroll
            for (int rr = 0; rr < 2; ++rr) {
                int m = mw*32 + t*16 + g + rr*8;
                buf[m*129 + c]     = acc[t][j][rr*2]   + b0v;
                buf[m*129 + c + 1] = acc[t][j][rr*2+1] + b1v;
            }
    }
    __syncthreads();
    for (int idx = tid; idx < 128*128; idx += 256) {
        int m = idx & 127, n = idx >> 7;
        out[(size_t)b*CH*HWQ + (size_t)n*HWQ + q0 + m] = buf[m*129 + n];
    }
}

// ============================================================================
extern "C" void kernel_launch(void* const* d_in, const int* in_sizes, int n_in,
                              void* d_out, int out_size)
{
    const float* nbr    = (const float*)d_in[0];
    const float* ext    = (const float*)d_in[1];
    const float* flow   = (const float*)d_in[2];
    const float* W_off  = (const float*)d_in[3];
    const float* b_off  = (const float*)d_in[4];
    const float* W_attn = (const float*)d_in[5];
    const float* b_attn = (const float*)d_in[6];
    const float* W_val  = (const float*)d_in[7];
    const float* b_val  = (const float*)d_in[8];
    const float* W_out  = (const float*)d_in[9];
    const float* b_out  = (const float*)d_in[10];
    float* out = (float*)d_out;

    const int SM_K1 = 2*K1_STG*4;
    const int SM_KV = 2*KV_STG*4;
    const int SM_KO = 2*KO_STG*4;

    cudaFuncSetAttribute(k1_offattn, cudaFuncAttributeMaxDynamicSharedMemorySize, SM_K1);
    cudaFuncSetAttribute(k_val,      cudaFuncAttributeMaxDynamicSharedMemorySize, SM_KV);
    cudaFuncSetAttribute(k_out,      cudaFuncAttributeMaxDynamicSharedMemorySize, SM_KO);

    const int nblk = BATCH * HWQ / 128;   // 512

    prep_B    <<<48, 256>>>(W_off, W_attn);
    k1_offattn<<<nblk, 256, SM_K1>>>(ext, flow, b_off, b_attn);
    k_val     <<<nblk, 256, SM_KV>>>(nbr, W_val, b_val);
    k_gather  <<<BATCH * HWQ / 8, 256>>>();
    k_out     <<<nblk, 256, SM_KO>>>(W_out, b_out, out);
}